// round 2
// baseline (speedup 1.0000x reference)
#include <cuda_runtime.h>

// Phase-folded unitary: Utilde[m*16+k] = (re, im) of U[m][k] * (-i)^popcount(k)
__device__ float2 g_U[256];

// ---------------------------------------------------------------------------
// Kernel 1: build the 16x16 unitary of the StronglyEntanglingLayers circuit.
// 16 threads, each propagates one basis column through 6 layers in registers.
// ---------------------------------------------------------------------------
__global__ void build_unitary(const float* __restrict__ rot) {
    int col = threadIdx.x;
    if (col >= 16) return;

    float sr[16], si[16];
#pragma unroll
    for (int k = 0; k < 16; k++) { sr[k] = 0.f; si[k] = 0.f; }
    sr[col] = 1.f;

#pragma unroll
    for (int l = 0; l < 6; l++) {
        // --- Rot(phi, theta, omega) on each qubit ---
#pragma unroll
        for (int q = 0; q < 4; q++) {
            const float phi   = rot[(l * 4 + q) * 3 + 0];
            const float theta = rot[(l * 4 + q) * 3 + 1];
            const float omega = rot[(l * 4 + q) * 3 + 2];
            float st, ct;
            __sincosf(0.5f * theta, &st, &ct);
            float epr, epi;                       // ep = exp(-i(phi+omega)/2)
            __sincosf(-0.5f * (phi + omega), &epi, &epr);
            float emr, emi;                       // em = exp(+i(phi-omega)/2)
            __sincosf(0.5f * (phi - omega), &emi, &emr);

            const float u00r =  epr * ct, u00i =  epi * ct;   // ep*ct
            const float u01r = -emr * st, u01i = -emi * st;   // -em*st
            const float u10r =  emr * st, u10i = -emi * st;   // conj(em)*st
            const float u11r =  epr * ct, u11i = -epi * ct;   // conj(ep)*ct

            const int mask = 8 >> q;  // qubit q lives in bit (3-q)
#pragma unroll
            for (int k = 0; k < 16; k++) {
                if (k & mask) continue;
                const int k1 = k | mask;
                const float ar = sr[k],  ai = si[k];
                const float br = sr[k1], bi = si[k1];
                sr[k]  = u00r * ar - u00i * ai + u01r * br - u01i * bi;
                si[k]  = u00r * ai + u00i * ar + u01r * bi + u01i * br;
                sr[k1] = u10r * ar - u10i * ai + u11r * br - u11i * bi;
                si[k1] = u10r * ai + u10i * ar + u11r * bi + u11i * br;
            }
        }
        // --- CNOT ring: control q -> target (q + r) % 4, applied sequentially ---
        const int r = l % 3 + 1;
#pragma unroll
        for (int q = 0; q < 4; q++) {
            const int t  = (q + r) & 3;
            const int mc = 8 >> q;
            const int mt = 8 >> t;
#pragma unroll
            for (int k = 0; k < 16; k++) {
                if ((k & mc) && !(k & mt)) {
                    const int k2 = k | mt;
                    float tmp;
                    tmp = sr[k]; sr[k] = sr[k2]; sr[k2] = tmp;
                    tmp = si[k]; si[k] = si[k2]; si[k2] = tmp;
                }
            }
        }
    }

    // Fold (-i)^popcount(col) into this column.
    const int pc = __popc(col) & 3;
#pragma unroll
    for (int m = 0; m < 16; m++) {
        const float a = sr[m], b = si[m];
        float nr, ni;
        if      (pc == 0) { nr =  a; ni =  b; }
        else if (pc == 1) { nr =  b; ni = -a; }   // *(-i)
        else if (pc == 2) { nr = -a; ni = -b; }   // *(-1)
        else              { nr = -b; ni =  a; }   // *(+i)
        g_U[m * 16 + col] = make_float2(nr, ni);
    }
}

// ---------------------------------------------------------------------------
// Kernel 2: one thread per sample.
//   p = (t0 x t1) x (t2 x t3) real 16-vector, w = Utilde * p (complex x real),
//   out_q = sum_m sign(q,m) * |w_m|^2
// ---------------------------------------------------------------------------
__global__ void __launch_bounds__(256) qc_forward(const float4* __restrict__ x,
                                                  float4* __restrict__ out,
                                                  int B) {
    __shared__ float2 sU[256];
    const int tid = threadIdx.x;
    sU[tid] = g_U[tid];
    __syncthreads();

    const int i = blockIdx.x * blockDim.x + tid;
    if (i >= B) return;

    const float4 xx = x[i];
    float c0, s0, c1, s1, c2, s2, c3, s3;
    __sincosf(0.5f * xx.x, &s0, &c0);
    __sincosf(0.5f * xx.y, &s1, &c1);
    __sincosf(0.5f * xx.z, &s2, &c2);
    __sincosf(0.5f * xx.w, &s3, &c3);

    // p[k] = t0[k>>3] * t1[(k>>2)&1] * t2[(k>>1)&1] * t3[k&1]
    float p01[4], p23[4], p[16];
    p01[0] = c0 * c1; p01[1] = c0 * s1; p01[2] = s0 * c1; p01[3] = s0 * s1;
    p23[0] = c2 * c3; p23[1] = c2 * s3; p23[2] = s2 * c3; p23[3] = s2 * s3;
#pragma unroll
    for (int a = 0; a < 4; a++)
#pragma unroll
        for (int b = 0; b < 4; b++)
            p[a * 4 + b] = p01[a] * p23[b];

    float n[16];
#pragma unroll
    for (int m = 0; m < 16; m++) {
        float wr = 0.f, wi = 0.f;
#pragma unroll
        for (int k = 0; k < 16; k++) {
            const float2 u = sU[m * 16 + k];
            wr = fmaf(u.x, p[k], wr);
            wi = fmaf(u.y, p[k], wi);
        }
        n[m] = wr * wr + wi * wi;
    }

    float o0 = 0.f, o1 = 0.f, o2 = 0.f, o3 = 0.f;
#pragma unroll
    for (int m = 0; m < 16; m++) {
        o0 += (m & 8) ? -n[m] : n[m];
        o1 += (m & 4) ? -n[m] : n[m];
        o2 += (m & 2) ? -n[m] : n[m];
        o3 += (m & 1) ? -n[m] : n[m];
    }
    out[i] = make_float4(o0, o1, o2, o3);
}

// ---------------------------------------------------------------------------
extern "C" void kernel_launch(void* const* d_in, const int* in_sizes, int n_in,
                              void* d_out, int out_size) {
    // Identify inputs by size (inputs: B*4 floats; rotations: 72 floats).
    const float* d_x   = (const float*)d_in[0];
    const float* d_rot = (const float*)d_in[1];
    int nx = in_sizes[0];
    if (n_in >= 2 && in_sizes[0] == 72) {   // order swapped
        d_x   = (const float*)d_in[1];
        d_rot = (const float*)d_in[0];
        nx    = in_sizes[1];
    }
    const int B = nx / 4;

    build_unitary<<<1, 32>>>(d_rot);
    const int threads = 256;
    const int blocks  = (B + threads - 1) / threads;
    qc_forward<<<blocks, threads>>>((const float4*)d_x, (float4*)d_out, B);
}

// round 5
// speedup vs baseline: 1.1236x; 1.1236x over previous
#include <cuda_runtime.h>

typedef unsigned long long u64;

// W coefficients: g_W2[m*4 + q] = (W[q][m], W[q][m]) duplicated pair.
// m = m0*27 + m1*9 + m2*3 + m3, basis per qubit: (1, cos x_q, sin x_q).
__device__ float2 g_W2[324];

// ---------------------------------------------------------------------------
// Kernel 1: build W[4][81] from the rotation parameters. One block, 384 thr.
//   A: 72 threads fill sincos table
//   B: 16 threads propagate unitary columns (phase-folded)
//   C: A_q[j,k] = sum_m z_q[m] (Ur[m,j]Ur[m,k] + Ui[m,j]Ui[m,k])
//   D: W[q][m] = (1/16) * signed sum of 16 A entries (sparse basis change)
// ---------------------------------------------------------------------------
__global__ void __launch_bounds__(384) build_W(const float* __restrict__ rot) {
    __shared__ float2 ssc[72];     // (sin, cos) per derived angle
    __shared__ float2 sU[256];     // Utilde[m*16 + col]
    __shared__ float  sA[1024];    // A[q][j*16+k]

    const int t = threadIdx.x;

    // --- Stage A: sincos table -------------------------------------------
    if (t < 72) {
        const int g = t / 3, c = t % 3;
        const float phi   = rot[g * 3 + 0];
        const float theta = rot[g * 3 + 1];
        const float omega = rot[g * 3 + 2];
        float ang;
        if      (c == 0) ang =  0.5f * theta;
        else if (c == 1) ang = -0.5f * (phi + omega);
        else             ang =  0.5f * (phi - omega);
        float s, cc;
        __sincosf(ang, &s, &cc);
        ssc[t] = make_float2(s, cc);
    }
    __syncthreads();

    // --- Stage B: column propagation -------------------------------------
    if (t < 16) {
        const int col = t;
        float sr[16], si[16];
#pragma unroll
        for (int k = 0; k < 16; k++) { sr[k] = 0.f; si[k] = 0.f; }
        sr[col] = 1.f;

#pragma unroll
        for (int l = 0; l < 6; l++) {
#pragma unroll
            for (int q = 0; q < 4; q++) {
                const int g = l * 4 + q;
                const float st  = ssc[g * 3 + 0].x, ct  = ssc[g * 3 + 0].y;
                const float epi = ssc[g * 3 + 1].x, epr = ssc[g * 3 + 1].y;
                const float emi = ssc[g * 3 + 2].x, emr = ssc[g * 3 + 2].y;

                const float u00r =  epr * ct, u00i =  epi * ct;
                const float u01r = -emr * st, u01i = -emi * st;
                const float u10r =  emr * st, u10i = -emi * st;
                const float u11r =  epr * ct, u11i = -epi * ct;

                const int mask = 8 >> q;
#pragma unroll
                for (int k = 0; k < 16; k++) {
                    if (k & mask) continue;
                    const int k1 = k | mask;
                    const float ar = sr[k],  ai = si[k];
                    const float br = sr[k1], bi = si[k1];
                    sr[k]  = u00r * ar - u00i * ai + u01r * br - u01i * bi;
                    si[k]  = u00r * ai + u00i * ar + u01r * bi + u01i * br;
                    sr[k1] = u10r * ar - u10i * ai + u11r * br - u11i * bi;
                    si[k1] = u10r * ai + u10i * ar + u11r * bi + u11i * br;
                }
            }
            const int r = l % 3 + 1;
#pragma unroll
            for (int q = 0; q < 4; q++) {
                const int tq = (q + r) & 3;
                const int mc = 8 >> q;
                const int mt = 8 >> tq;
#pragma unroll
                for (int k = 0; k < 16; k++) {
                    if ((k & mc) && !(k & mt)) {
                        const int k2 = k | mt;
                        float tmp;
                        tmp = sr[k]; sr[k] = sr[k2]; sr[k2] = tmp;
                        tmp = si[k]; si[k] = si[k2]; si[k2] = tmp;
                    }
                }
            }
        }
        // fold (-i)^popcount(col)
        const int pc = __popc(col) & 3;
#pragma unroll
        for (int m = 0; m < 16; m++) {
            const float a = sr[m], b = si[m];
            float nr, ni;
            if      (pc == 0) { nr =  a; ni =  b; }
            else if (pc == 1) { nr =  b; ni = -a; }
            else if (pc == 2) { nr = -a; ni = -b; }
            else              { nr = -b; ni =  a; }
            sU[m * 16 + col] = make_float2(nr, ni);
        }
    }
    __syncthreads();

    // --- Stage C: A_q[j,k] -----------------------------------------------
    for (int idx = t; idx < 1024; idx += 384) {
        const int qo = idx >> 8;
        const int jk = idx & 255;
        const int j = jk >> 4, k = jk & 15;
        const int bitpos = 3 - qo;
        float acc = 0.f;
#pragma unroll
        for (int m = 0; m < 16; m++) {
            const float2 uj = sU[m * 16 + j];
            const float2 uk = sU[m * 16 + k];
            const float v = uj.x * uk.x + uj.y * uk.y;
            acc += ((m >> bitpos) & 1) ? -v : v;
        }
        sA[idx] = acc;
    }
    __syncthreads();

    // --- Stage D: basis change -> W --------------------------------------
    if (t < 324) {
        const int m  = t >> 2;    // 0..80
        const int qo = t & 3;
        int md[4];
        md[0] = m / 27; md[1] = (m / 9) % 3; md[2] = (m / 3) % 3; md[3] = m % 3;

        float acc = 0.f;
#pragma unroll
        for (int sel = 0; sel < 16; sel++) {
            int j = 0, k = 0;
            float sgn = 1.f;
#pragma unroll
            for (int q = 0; q < 4; q++) {
                const int b = (sel >> (3 - q)) & 1;
                int jkq;
                if (md[q] == 0) {
                    jkq = b ? 3 : 0;
                } else if (md[q] == 1) {
                    jkq = b ? 3 : 0;
                    if (b) sgn = -sgn;
                } else {
                    jkq = b ? 2 : 1;
                }
                j |= (jkq >> 1) << (3 - q);
                k |= (jkq & 1)  << (3 - q);
            }
            acc += sgn * sA[qo * 256 + j * 16 + k];
        }
        const float w = acc * 0.0625f;
        g_W2[m * 4 + qo] = make_float2(w, w);
    }
}

// ---------------------------------------------------------------------------
// Packed f32x2 helpers
// ---------------------------------------------------------------------------
__device__ __forceinline__ u64 pk(float lo, float hi) {
    u64 r; asm("mov.b64 %0, {%1, %2};" : "=l"(r) : "f"(lo), "f"(hi)); return r;
}
__device__ __forceinline__ void upk(float& lo, float& hi, u64 v) {
    asm("mov.b64 {%0, %1}, %2;" : "=f"(lo), "=f"(hi) : "l"(v));
}
__device__ __forceinline__ u64 pmul(u64 a, u64 b) {
    u64 d; asm("mul.rn.f32x2 %0, %1, %2;" : "=l"(d) : "l"(a), "l"(b)); return d;
}
__device__ __forceinline__ u64 pfma(u64 a, u64 b, u64 c) {
    u64 d; asm("fma.rn.f32x2 %0, %1, %2, %3;" : "=l"(d) : "l"(a), "l"(b), "l"(c)); return d;
}

// ---------------------------------------------------------------------------
// Kernel 2: one thread handles samples i and i+halfB (packed in f32x2 lanes).
// ---------------------------------------------------------------------------
__global__ void __launch_bounds__(128) qc_forward(const float4* __restrict__ x,
                                                  float4* __restrict__ out,
                                                  int halfB) {
    __shared__ __align__(16) u64 sW[324];
    const int tid = threadIdx.x;
    for (int idx = tid; idx < 324; idx += 128)
        sW[idx] = ((const u64*)g_W2)[idx];
    __syncthreads();

    const int i = blockIdx.x * 128 + tid;
    if (i >= halfB) return;

    const float4 xa = x[i];
    const float4 xb = x[i + halfB];

    float Ca0, Sa0, Ca1, Sa1, Ca2, Sa2, Ca3, Sa3;
    float Cb0, Sb0, Cb1, Sb1, Cb2, Sb2, Cb3, Sb3;
    __sincosf(xa.x, &Sa0, &Ca0);  __sincosf(xa.y, &Sa1, &Ca1);
    __sincosf(xa.z, &Sa2, &Ca2);  __sincosf(xa.w, &Sa3, &Ca3);
    __sincosf(xb.x, &Sb0, &Cb0);  __sincosf(xb.y, &Sb1, &Cb1);
    __sincosf(xb.z, &Sb2, &Cb2);  __sincosf(xb.w, &Sb3, &Cb3);

    const u64 C0p = pk(Ca0, Cb0), S0p = pk(Sa0, Sb0);
    const u64 C1p = pk(Ca1, Cb1), S1p = pk(Sa1, Sb1);
    const u64 C2p = pk(Ca2, Cb2), S2p = pk(Sa2, Sb2);
    const u64 C3p = pk(Ca3, Cb3), S3p = pk(Sa3, Sb3);
    const u64 ONE = 0x3F8000003F800000ULL;

    // monomials over qubits 2,3:  index m2*3+m3
    u64 m23[9];
    m23[0] = ONE;
    m23[1] = C3p;             m23[2] = S3p;
    m23[3] = C2p;             m23[6] = S2p;
    m23[4] = pmul(C2p, C3p);  m23[5] = pmul(C2p, S3p);
    m23[7] = pmul(S2p, C3p);  m23[8] = pmul(S2p, S3p);

    u64 e0[3]; e0[0] = ONE; e0[1] = C0p; e0[2] = S0p;
    u64 e1[3]; e1[0] = ONE; e1[1] = C1p; e1[2] = S1p;

    u64 acc0 = 0ULL, acc1 = 0ULL, acc2 = 0ULL, acc3 = 0ULL;

#pragma unroll
    for (int m0 = 0; m0 < 3; m0++) {
#pragma unroll
        for (int m1 = 0; m1 < 3; m1++) {
            u64 base01;
            if (m0 == 0 && m1 == 0)      base01 = ONE;
            else if (m0 == 0)            base01 = e1[m1];
            else if (m1 == 0)            base01 = e0[m0];
            else                         base01 = pmul(e0[m0], e1[m1]);
#pragma unroll
            for (int j9 = 0; j9 < 9; j9++) {
                u64 mono;
                if (m0 == 0 && m1 == 0)  mono = m23[j9];
                else if (j9 == 0)        mono = base01;
                else                     mono = pmul(base01, m23[j9]);
                const int j = (m0 * 3 + m1) * 9 + j9;
                const ulonglong2 wa = *(const ulonglong2*)&sW[j * 4];
                const ulonglong2 wb = *(const ulonglong2*)&sW[j * 4 + 2];
                acc0 = pfma(mono, wa.x, acc0);
                acc1 = pfma(mono, wa.y, acc1);
                acc2 = pfma(mono, wb.x, acc2);
                acc3 = pfma(mono, wb.y, acc3);
            }
        }
    }

    float o0a, o0b, o1a, o1b, o2a, o2b, o3a, o3b;
    upk(o0a, o0b, acc0);
    upk(o1a, o1b, acc1);
    upk(o2a, o2b, acc2);
    upk(o3a, o3b, acc3);

    out[i]         = make_float4(o0a, o1a, o2a, o3a);
    out[i + halfB] = make_float4(o0b, o1b, o2b, o3b);
}

// ---------------------------------------------------------------------------
extern "C" void kernel_launch(void* const* d_in, const int* in_sizes, int n_in,
                              void* d_out, int out_size) {
    const float* d_x   = (const float*)d_in[0];
    const float* d_rot = (const float*)d_in[1];
    int nx = in_sizes[0];
    if (n_in >= 2 && in_sizes[0] == 72) {
        d_x   = (const float*)d_in[1];
        d_rot = (const float*)d_in[0];
        nx    = in_sizes[1];
    }
    const int B = nx / 4;
    const int halfB = B / 2;

    build_W<<<1, 384>>>(d_rot);
    const int threads = 128;
    const int blocks  = (halfB + threads - 1) / threads;
    qc_forward<<<blocks, threads>>>((const float4*)d_x, (float4*)d_out, halfB);
}

// round 8
// speedup vs baseline: 1.7964x; 1.5988x over previous
#include <cuda_runtime.h>

typedef unsigned long long u64;

// W coefficients: g_W4[m] = float4(W[0][m], W[1][m], W[2][m], W[3][m]),
// m = m0*27 + m1*9 + m2*3 + m3, basis per qubit: (1, cos x_q, sin x_q).
__device__ float4 g_W4[81];

// ---------------------------------------------------------------------------
// Compile-time CNOT permutation tables.
// Qubit q lives in bit (3-q). CNOT(c,t): flip bit(3-t) if bit(3-c) set (linear).
// P_l = index-relabel map accumulated over CNOT layers 0..l-1.
// ---------------------------------------------------------------------------
struct Tables {
    int pcol[7][4];   // P_l applied to basis indices {1,2,4,8}
    int xm[6][4];     // P_l^{-1}(8>>q): shuffle-xor mask for gate (l,q)
};

__host__ __device__ constexpr int cnot_k(int k, int c, int t) {
    return ((k >> (3 - c)) & 1) ? (k ^ (8 >> t)) : k;
}
__host__ __device__ constexpr int layer_perm(int k, int l) {
    const int r = l % 3 + 1;
    for (int q = 0; q < 4; q++) k = cnot_k(k, q, (q + r) & 3);
    return k;
}
__host__ __device__ constexpr Tables make_tables() {
    Tables T{};
    int P[7][16]{};
    for (int a = 0; a < 16; a++) P[0][a] = a;
    for (int l = 0; l < 6; l++)
        for (int a = 0; a < 16; a++) P[l + 1][a] = layer_perm(P[l][a], l);
    for (int l = 0; l < 7; l++)
        for (int b = 0; b < 4; b++) T.pcol[l][b] = P[l][1 << b];
    for (int l = 0; l < 6; l++)
        for (int q = 0; q < 4; q++) {
            const int m = 8 >> q;
            for (int a = 0; a < 16; a++)
                if (P[l][a] == m) T.xm[l][q] = a;
        }
    return T;
}

// ---------------------------------------------------------------------------
// Kernel 1: build W[4][81]. One block, 256 threads.
//   A: 72 threads fill sincos table
//   B: 256 threads = 16 cols x 16 amps; shuffle-butterfly gate propagation
//   C: A_q[j,k] = sum_m z_q[m] (Ur[m,j]Ur[m,k] + Ui[m,j]Ui[m,k])
//   D: W[q][m] = (1/16) * signed sum of 16 A entries
// ---------------------------------------------------------------------------
__global__ void __launch_bounds__(256) build_W(const float* __restrict__ rot) {
    // Function-scope constexpr: compile-time evaluated, legal in device code.
    constexpr Tables TBL = make_tables();

    __shared__ float2 ssc[72];     // (sin, cos) per derived angle
    __shared__ float2 sU[256];     // Utilde[m*16 + col]
    __shared__ float  sA[1024];    // A[q][j*16+k]

    const int t = threadIdx.x;

    // --- Stage A: sincos table -------------------------------------------
    if (t < 72) {
        const int g = t / 3, c = t % 3;
        const float phi   = rot[g * 3 + 0];
        const float theta = rot[g * 3 + 1];
        const float omega = rot[g * 3 + 2];
        float ang;
        if      (c == 0) ang =  0.5f * theta;
        else if (c == 1) ang = -0.5f * (phi + omega);
        else             ang =  0.5f * (phi - omega);
        float s, cc;
        __sincosf(ang, &s, &cc);
        ssc[t] = make_float2(s, cc);
    }
    __syncthreads();

    // --- Stage B: 256-way column propagation ------------------------------
    {
        const int col = t >> 4;       // which basis column this thread propagates
        const int a   = t & 15;       // initial amplitude label

        float vr = (a == col) ? 1.f : 0.f;
        float vi = 0.f;

#pragma unroll
        for (int l = 0; l < 6; l++) {
            // current amplitude index under P_l (xor of compile-time columns)
            const int kl = ((a & 1) ? TBL.pcol[l][0] : 0)
                         ^ ((a & 2) ? TBL.pcol[l][1] : 0)
                         ^ ((a & 4) ? TBL.pcol[l][2] : 0)
                         ^ ((a & 8) ? TBL.pcol[l][3] : 0);
#pragma unroll
            for (int q = 0; q < 4; q++) {
                const int g = l * 4 + q;
                const float st  = ssc[g * 3 + 0].x, ct  = ssc[g * 3 + 0].y;
                const float epi = ssc[g * 3 + 1].x, epr = ssc[g * 3 + 1].y;
                const float emi = ssc[g * 3 + 2].x, emr = ssc[g * 3 + 2].y;

                const float u00r =  epr * ct, u00i =  epi * ct;
                const float u01r = -emr * st, u01i = -emi * st;
                const float u10r =  emr * st, u10i = -emi * st;
                const float u11r =  epr * ct, u11i = -epi * ct;

                const bool hi = (kl >> (3 - q)) & 1;
                const int xmask = TBL.xm[l][q];  // partner lane = lane ^ xmask (<16)

                const float pr = __shfl_xor_sync(0xFFFFFFFF, vr, xmask);
                const float pi = __shfl_xor_sync(0xFFFFFFFF, vi, xmask);

                const float lor = hi ? pr : vr, loi = hi ? pi : vi;
                const float hir = hi ? vr : pr, hii = hi ? vi : pi;
                const float cAr = hi ? u10r : u00r, cAi = hi ? u10i : u00i;
                const float cBr = hi ? u11r : u01r, cBi = hi ? u11i : u01i;

                vr = cAr * lor - cAi * loi + cBr * hir - cBi * hii;
                vi = cAr * loi + cAi * lor + cBr * hii + cBi * hir;
            }
        }

        // final amplitude index under P_6
        const int m = ((a & 1) ? TBL.pcol[6][0] : 0)
                    ^ ((a & 2) ? TBL.pcol[6][1] : 0)
                    ^ ((a & 4) ? TBL.pcol[6][2] : 0)
                    ^ ((a & 8) ? TBL.pcol[6][3] : 0);

        // fold (-i)^popcount(col) into this column
        const int pc = __popc(col) & 3;
        float nr, ni;
        if      (pc == 0) { nr =  vr; ni =  vi; }
        else if (pc == 1) { nr =  vi; ni = -vr; }
        else if (pc == 2) { nr = -vr; ni = -vi; }
        else              { nr = -vi; ni =  vr; }
        sU[m * 16 + col] = make_float2(nr, ni);
    }
    __syncthreads();

    // --- Stage C: A_q[j,k] -----------------------------------------------
#pragma unroll
    for (int idx = t; idx < 1024; idx += 256) {
        const int qo = idx >> 8;
        const int jk = idx & 255;
        const int j = jk >> 4, k = jk & 15;
        const int bitpos = 3 - qo;
        float acc = 0.f;
#pragma unroll
        for (int m = 0; m < 16; m++) {
            const float2 uj = sU[m * 16 + j];
            const float2 uk = sU[m * 16 + k];
            const float v = uj.x * uk.x + uj.y * uk.y;
            acc += ((m >> bitpos) & 1) ? -v : v;
        }
        sA[idx] = acc;
    }
    __syncthreads();

    // --- Stage D: basis change -> W --------------------------------------
    for (int idx = t; idx < 324; idx += 256) {
        const int m  = idx >> 2;    // 0..80
        const int qo = idx & 3;
        int md[4];
        md[0] = m / 27; md[1] = (m / 9) % 3; md[2] = (m / 3) % 3; md[3] = m % 3;

        float acc = 0.f;
#pragma unroll
        for (int sel = 0; sel < 16; sel++) {
            int j = 0, k = 0;
            float sgn = 1.f;
#pragma unroll
            for (int q = 0; q < 4; q++) {
                const int b = (sel >> (3 - q)) & 1;
                int jkq;
                if (md[q] == 0) {
                    jkq = b ? 3 : 0;
                } else if (md[q] == 1) {
                    jkq = b ? 3 : 0;
                    if (b) sgn = -sgn;
                } else {
                    jkq = b ? 2 : 1;
                }
                j |= (jkq >> 1) << (3 - q);
                k |= (jkq & 1)  << (3 - q);
            }
            acc += sgn * sA[qo * 256 + j * 16 + k];
        }
        ((float*)g_W4)[m * 4 + qo] = acc * 0.0625f;
    }
}

// ---------------------------------------------------------------------------
// Packed f32x2 helpers
// ---------------------------------------------------------------------------
__device__ __forceinline__ u64 pk2(float lo, float hi) {
    u64 r; asm("mov.b64 %0, {%1, %2};" : "=l"(r) : "f"(lo), "f"(hi)); return r;
}
__device__ __forceinline__ void upk(float& lo, float& hi, u64 v) {
    asm("mov.b64 {%0, %1}, %2;" : "=f"(lo), "=f"(hi) : "l"(v));
}
__device__ __forceinline__ u64 pmul(u64 a, u64 b) {
    u64 d; asm("mul.rn.f32x2 %0, %1, %2;" : "=l"(d) : "l"(a), "l"(b)); return d;
}
__device__ __forceinline__ u64 pfma(u64 a, u64 b, u64 c) {
    u64 d; asm("fma.rn.f32x2 %0, %1, %2, %3;" : "=l"(d) : "l"(a), "l"(b), "l"(c)); return d;
}

// ---------------------------------------------------------------------------
// Kernel 2: one thread = one sample. f32x2 lanes pack the q-axis:
// monomials duplicated across lanes; acc01 = (out_q0, out_q1), acc23 = (q2,q3).
// ---------------------------------------------------------------------------
__global__ void __launch_bounds__(256) qc_forward(const float4* __restrict__ x,
                                                  float4* __restrict__ out,
                                                  int B) {
    __shared__ __align__(16) float4 sW4[81];
    const int tid = threadIdx.x;
    if (tid < 81) sW4[tid] = g_W4[tid];
    __syncthreads();

    const int i = blockIdx.x * 256 + tid;
    if (i >= B) return;

    const float4 xx = x[i];
    float c0, s0, c1, s1, c2, s2, c3, s3;
    __sincosf(xx.x, &s0, &c0);
    __sincosf(xx.y, &s1, &c1);
    __sincosf(xx.z, &s2, &c2);
    __sincosf(xx.w, &s3, &c3);

    const u64 C0p = pk2(c0, c0), S0p = pk2(s0, s0);
    const u64 C1p = pk2(c1, c1), S1p = pk2(s1, s1);
    const u64 C2p = pk2(c2, c2), S2p = pk2(s2, s2);
    const u64 C3p = pk2(c3, c3), S3p = pk2(s3, s3);
    const u64 ONE = 0x3F8000003F800000ULL;

    // monomials over qubits 2,3: index m2*3+m3
    u64 m23[9];
    m23[0] = ONE;
    m23[1] = C3p;             m23[2] = S3p;
    m23[3] = C2p;             m23[6] = S2p;
    m23[4] = pmul(C2p, C3p);  m23[5] = pmul(C2p, S3p);
    m23[7] = pmul(S2p, C3p);  m23[8] = pmul(S2p, S3p);

    u64 e0[3]; e0[0] = ONE; e0[1] = C0p; e0[2] = S0p;
    u64 e1[3]; e1[0] = ONE; e1[1] = C1p; e1[2] = S1p;

    u64 acc01 = 0ULL, acc23 = 0ULL;

#pragma unroll
    for (int m0 = 0; m0 < 3; m0++) {
#pragma unroll
        for (int m1 = 0; m1 < 3; m1++) {
            u64 base01;
            if (m0 == 0 && m1 == 0)      base01 = ONE;
            else if (m0 == 0)            base01 = e1[m1];
            else if (m1 == 0)            base01 = e0[m0];
            else                         base01 = pmul(e0[m0], e1[m1]);
#pragma unroll
            for (int j9 = 0; j9 < 9; j9++) {
                u64 mono;
                if (m0 == 0 && m1 == 0)  mono = m23[j9];
                else if (j9 == 0)        mono = base01;
                else                     mono = pmul(base01, m23[j9]);
                const int j = (m0 * 3 + m1) * 9 + j9;
                const ulonglong2 wv = ((const ulonglong2*)sW4)[j];
                acc01 = pfma(mono, wv.x, acc01);   // lanes (W0, W1)
                acc23 = pfma(mono, wv.y, acc23);   // lanes (W2, W3)
            }
        }
    }

    float o0, o1, o2, o3;
    upk(o0, o1, acc01);
    upk(o2, o3, acc23);
    out[i] = make_float4(o0, o1, o2, o3);
}

// ---------------------------------------------------------------------------
extern "C" void kernel_launch(void* const* d_in, const int* in_sizes, int n_in,
                              void* d_out, int out_size) {
    const float* d_x   = (const float*)d_in[0];
    const float* d_rot = (const float*)d_in[1];
    int nx = in_sizes[0];
    if (n_in >= 2 && in_sizes[0] == 72) {
        d_x   = (const float*)d_in[1];
        d_rot = (const float*)d_in[0];
        nx    = in_sizes[1];
    }
    const int B = nx / 4;

    build_W<<<1, 256>>>(d_rot);
    const int threads = 256;
    const int blocks  = (B + threads - 1) / threads;
    qc_forward<<<blocks, threads>>>((const float4*)d_x, (float4*)d_out, B);
}